// round 10
// baseline (speedup 1.0000x reference)
#include <cuda_runtime.h>
#include <cuda_fp16.h>
#include <mma.h>
#include <math.h>
#include <stdint.h>

using namespace nvcuda;

// Problem constants
#define N_TOK 8192
#define DIM   512
#define FDIM  2048
#define NEXP  8
#define NASS  (N_TOK * 2)
#define EPS_F 2.220446049250313e-16f

// Dynamic smem layout (bytes):
//   As: 2 stages x 256 rows x 40 halves = 40960
//   Bs: 2 stages x  32 rows x 136 halves = 17408
//   scr: 16 warps x 256 floats           = 16384
#define AS_HALVES   (256 * 40)
#define BS_HALVES   (32 * 136)
#define BS_BYTE0    (2 * AS_HALVES * 2)
#define SCR_BYTE0   (BS_BYTE0 + 2 * BS_HALVES * 2)
#define SMEM_TOTAL  (SCR_BYTE0 + 16 * 256 * 4)

// ---------------- scratch (static device globals) ----------------
__device__ float g_H[(size_t)NASS * FDIM];   // relu(x@W1+b1), fp32
__device__ float g_O[(size_t)NASS * DIM];    // gate*exp(h@W2+b2), fp32
__device__ int   g_cnt[NEXP];
__device__ int   g_off[NEXP];
__device__ int   g_cursor[NEXP];
__device__ int   g_tok_e[N_TOK * 2];
__device__ float g_tok_g[N_TOK * 2];
__device__ int   g_row_tok[NASS];
__device__ float g_row_gate[NASS];
__device__ int   g_ass_row[N_TOK * 2];

// ---------------- gating / routing (validated, unchanged) ----------------
__global__ void zero_kernel() {
    int t = threadIdx.x;
    if (t < NEXP) g_cnt[t] = 0;
}

__global__ void gate_kernel(const float* __restrict__ x, const float* __restrict__ Wg) {
    __shared__ float WgS[NEXP][DIM];
    int tid = threadIdx.x;
    for (int i = tid; i < DIM * NEXP; i += 256) {
        int d = i >> 3, e = i & 7;
        WgS[e][d] = Wg[i];
    }
    __syncthreads();
    int warp = tid >> 5, lane = tid & 31;
    int t = blockIdx.x * 8 + warp;
    float acc[NEXP];
#pragma unroll
    for (int e = 0; e < NEXP; e++) acc[e] = 0.f;
    const float* xr = x + (size_t)t * DIM;
    for (int j = lane; j < DIM; j += 32) {
        float xv = xr[j];
#pragma unroll
        for (int e = 0; e < NEXP; e++) acc[e] += xv * WgS[e][j];
    }
#pragma unroll
    for (int e = 0; e < NEXP; e++) {
#pragma unroll
        for (int o = 16; o > 0; o >>= 1) acc[e] += __shfl_xor_sync(0xffffffffu, acc[e], o);
    }
    if (lane == 0) {
        float best = -INFINITY, sec = -INFINITY;
        int bi = 0, si = 0;
#pragma unroll
        for (int e = 0; e < NEXP; e++) {
            float v = acc[e];
            if (v > best)     { sec = best; si = bi; best = v; bi = e; }
            else if (v > sec) { sec = v; si = e; }
        }
        float e1 = expf(sec - best);
        float s  = 1.f + e1;
        g_tok_e[2 * t] = bi;  g_tok_e[2 * t + 1] = si;
        g_tok_g[2 * t] = 1.f / s;  g_tok_g[2 * t + 1] = e1 / s;
        atomicAdd(&g_cnt[bi], 1);
        atomicAdd(&g_cnt[si], 1);
    }
}

__global__ void prefix_kernel() {
    int o = 0;
    for (int e = 0; e < NEXP; e++) { g_off[e] = o; g_cursor[e] = o; o += g_cnt[e]; }
}

__global__ void assign_kernel() {
    int t = blockIdx.x * 256 + threadIdx.x;
    int e0 = g_tok_e[2 * t], e1 = g_tok_e[2 * t + 1];
    int r0 = atomicAdd(&g_cursor[e0], 1);
    int r1 = atomicAdd(&g_cursor[e1], 1);
    g_row_tok[r0] = t; g_row_gate[r0] = g_tok_g[2 * t];
    g_row_tok[r1] = t; g_row_gate[r1] = g_tok_g[2 * t + 1];
    g_ass_row[2 * t] = r0;
    g_ass_row[2 * t + 1] = r1;
}

// ---------------- WMMA fp16 GEMM: 256x128 CTA tile, 512 threads (16 warps = 8M x 2N) ----------------
// Per-warp tile 32x64 and per-thread register profile identical to the validated R9 kernel.
// C[m][n] = sum_k A[m][k]*B[k][n], KC=32, double-buffered dynamic smem, R6-proven loop order.
template<bool G1>
__global__ __launch_bounds__(512, 1) void moe_gemm_wmma(const float* __restrict__ x,
                                                        const float* __restrict__ W,
                                                        const float* __restrict__ bias) {
    constexpr int K    = G1 ? DIM : FDIM;
    constexpr int NOUT = G1 ? FDIM : DIM;
    constexpr int KT   = K / 32;

    extern __shared__ __align__(16) char smem[];
    __half* As  = (__half*)smem;                       // [2][256*40]
    __half* Bs  = (__half*)(smem + BS_BYTE0);          // [2][32*136]
    float*  scr = (float*)(smem + SCR_BYTE0);          // [16][256]

    int e   = blockIdx.z;
    int cnt = g_cnt[e];
    int m0  = blockIdx.y * 256;
    if (m0 >= cnt) return;
    int base = g_off[e];
    int n0   = blockIdx.x * 128;

    const float* Bb = W + (size_t)e * ((size_t)DIM * FDIM);

    int tid = threadIdx.x, wid = tid >> 5, lane = tid & 31;
    int wm = (wid & 7) * 32;     // 8 warps in M
    int wn = (wid >> 3) * 64;    // 2 warps in N

    // A-chunk source rows (gathered once): 2048 chunks = 256 rows x 8, 4/thread
    int tok[4];
#pragma unroll
    for (int q = 0; q < 4; q++) {
        int ch = q * 512 + tid;
        int arow = ch >> 3;
        int mr = m0 + arow; if (mr >= cnt) mr = cnt - 1;
        tok[q] = G1 ? g_row_tok[base + mr] : (base + mr);
    }

    float4 ra[4], rb[2];
    auto gload = [&](int kt) {
#pragma unroll
        for (int q = 0; q < 4; q++) {
            int ch = q * 512 + tid;
            int ac = ch & 7;
            const float* arow_p = G1 ? (x + (size_t)tok[q] * DIM)
                                     : (g_H + (size_t)tok[q] * FDIM);
            ra[q] = *(const float4*)(arow_p + kt * 32 + ac * 4);
        }
#pragma unroll
        for (int q = 0; q < 2; q++) {
            int ch = q * 512 + tid;
            int brow = ch >> 5, bc = ch & 31;   // 1024 chunks = 32 rows x 32
            rb[q] = *(const float4*)(Bb + (size_t)(kt * 32 + brow) * NOUT + n0 + bc * 4);
        }
    };
    auto sstore = [&](int s) {
        __half* as = As + s * AS_HALVES;
        __half* bs = Bs + s * BS_HALVES;
#pragma unroll
        for (int q = 0; q < 4; q++) {
            int ch = q * 512 + tid;
            int arow = ch >> 3, ac = ch & 7;
            __half2* ap = (__half2*)&as[arow * 40 + ac * 4];
            ap[0] = __floats2half2_rn(ra[q].x, ra[q].y);
            ap[1] = __floats2half2_rn(ra[q].z, ra[q].w);
        }
#pragma unroll
        for (int q = 0; q < 2; q++) {
            int ch = q * 512 + tid;
            int brow = ch >> 5, bc = ch & 31;
            __half2* bp = (__half2*)&bs[brow * 136 + bc * 4];
            bp[0] = __floats2half2_rn(rb[q].x, rb[q].y);
            bp[1] = __floats2half2_rn(rb[q].z, rb[q].w);
        }
    };

    wmma::fragment<wmma::accumulator, 16, 16, 16, float> acc[2][4];
#pragma unroll
    for (int mi = 0; mi < 2; mi++)
#pragma unroll
        for (int nj = 0; nj < 4; nj++) wmma::fill_fragment(acc[mi][nj], 0.f);

    gload(0);

#pragma unroll 1
    for (int kt = 0; kt < KT; kt++) {
        int s = kt & 1;
        __syncthreads();
        sstore(s);
        __syncthreads();
        if (kt + 1 < KT) gload(kt + 1);

        const __half* as = As + s * AS_HALVES;
        const __half* bs = Bs + s * BS_HALVES;
#pragma unroll
        for (int kk = 0; kk < 2; kk++) {
            wmma::fragment<wmma::matrix_a, 16, 16, 16, __half, wmma::row_major> af[2];
            wmma::fragment<wmma::matrix_b, 16, 16, 16, __half, wmma::row_major> bf[4];
#pragma unroll
            for (int mi = 0; mi < 2; mi++)
                wmma::load_matrix_sync(af[mi], &as[(wm + mi * 16) * 40 + kk * 16], 40);
#pragma unroll
            for (int nj = 0; nj < 4; nj++)
                wmma::load_matrix_sync(bf[nj], &bs[(kk * 16) * 136 + wn + nj * 16], 136);
#pragma unroll
            for (int mi = 0; mi < 2; mi++)
#pragma unroll
                for (int nj = 0; nj < 4; nj++)
                    wmma::mma_sync(acc[mi][nj], af[mi], bf[nj], acc[mi][nj]);
        }
    }

    // ---------------- vectorized epilogue via per-warp smem scratch ----------------
    __syncthreads();
    float* scrW = scr + wid * 256;
    const float* be = bias + (size_t)e * NOUT + n0;
    int rr = lane >> 2;            // rows 0..7
    int cc = (lane & 3) * 4;       // float4 column chunk
#pragma unroll
    for (int mi = 0; mi < 2; mi++) {
#pragma unroll
        for (int nj = 0; nj < 4; nj++) {
            wmma::store_matrix_sync(scrW, acc[mi][nj], 16, wmma::mem_row_major);
            __syncwarp();
            int mbase = m0 + wm + mi * 16;
#pragma unroll
            for (int h = 0; h < 2; h++) {
                int row = rr + h * 8;
                int m = mbase + row;
                if (m < cnt) {
                    int r = base + m;
                    int nc = wn + nj * 16 + cc;
                    float4 v = *(const float4*)&scrW[row * 16 + cc];
                    float4 bv = *(const float4*)&be[nc];
                    v.x += bv.x; v.y += bv.y; v.z += bv.z; v.w += bv.w;
                    if (G1) {
                        v.x = v.x > 0.f ? v.x : 0.f;
                        v.y = v.y > 0.f ? v.y : 0.f;
                        v.z = v.z > 0.f ? v.z : 0.f;
                        v.w = v.w > 0.f ? v.w : 0.f;
                        *(float4*)&g_H[(size_t)r * FDIM + n0 + nc] = v;
                    } else {
                        float gate = g_row_gate[r];
                        v.x = gate * __expf(v.x);
                        v.y = gate * __expf(v.y);
                        v.z = gate * __expf(v.z);
                        v.w = gate * __expf(v.w);
                        *(float4*)&g_O[(size_t)r * DIM + n0 + nc] = v;
                    }
                }
            }
            __syncwarp();
        }
    }
}

// ---------------- combine (validated) ----------------
__global__ void combine_kernel(float* __restrict__ out) {
    int i = blockIdx.x * 1024 + threadIdx.x;
    int t = i >> 9;
    int d = i & (DIM - 1);
    int r0 = g_ass_row[2 * t];
    int r1 = g_ass_row[2 * t + 1];
    float s = g_O[(size_t)r0 * DIM + d] + g_O[(size_t)r1 * DIM + d];
    out[i] = logf(s == 0.f ? EPS_F : s);
}

// ---------------- launch ----------------
extern "C" void kernel_launch(void* const* d_in, const int* in_sizes, int n_in,
                              void* d_out, int out_size) {
    const float* x  = (const float*)d_in[0];
    const float* Wg = (const float*)d_in[1];
    const float* W1 = (const float*)d_in[2];
    const float* b1 = (const float*)d_in[3];
    const float* W2 = (const float*)d_in[4];
    const float* b2 = (const float*)d_in[5];
    float* out = (float*)d_out;

    cudaFuncSetAttribute(moe_gemm_wmma<true>,  cudaFuncAttributeMaxDynamicSharedMemorySize, SMEM_TOTAL);
    cudaFuncSetAttribute(moe_gemm_wmma<false>, cudaFuncAttributeMaxDynamicSharedMemorySize, SMEM_TOTAL);

    zero_kernel<<<1, 32>>>();
    gate_kernel<<<N_TOK / 8, 256>>>(x, Wg);
    prefix_kernel<<<1, 1>>>();
    assign_kernel<<<N_TOK / 256, 256>>>();

    moe_gemm_wmma<true ><<<dim3(FDIM / 128, 32, NEXP), 512, SMEM_TOTAL>>>(x, W1, b1);
    moe_gemm_wmma<false><<<dim3(DIM  / 128, 32, NEXP), 512, SMEM_TOTAL>>>(x, W2, b2);

    combine_kernel<<<(N_TOK * DIM) / 1024, 1024>>>(out);
}

// round 11
// speedup vs baseline: 1.0051x; 1.0051x over previous
#include <cuda_runtime.h>
#include <cuda_fp16.h>
#include <mma.h>
#include <math.h>
#include <stdint.h>

using namespace nvcuda;

// Problem constants
#define N_TOK 8192
#define DIM   512
#define FDIM  2048
#define NEXP  8
#define NASS  (N_TOK * 2)
#define EPS_F 2.220446049250313e-16f

// ---------------- scratch (static device globals) ----------------
__device__ float g_H[(size_t)NASS * FDIM];   // relu(x@W1+b1), fp32
__device__ float g_O[(size_t)NASS * DIM];    // gate*exp(h@W2+b2), fp32
__device__ int   g_cnt[NEXP];
__device__ int   g_off[NEXP];
__device__ int   g_cursor[NEXP];
__device__ int   g_tok_e[N_TOK * 2];
__device__ float g_tok_g[N_TOK * 2];
__device__ int   g_row_tok[NASS];
__device__ float g_row_gate[NASS];
__device__ int   g_ass_row[N_TOK * 2];

// ---------------- gating / routing (validated, unchanged) ----------------
__global__ void zero_kernel() {
    int t = threadIdx.x;
    if (t < NEXP) g_cnt[t] = 0;
}

__global__ void gate_kernel(const float* __restrict__ x, const float* __restrict__ Wg) {
    __shared__ float WgS[NEXP][DIM];
    int tid = threadIdx.x;
    for (int i = tid; i < DIM * NEXP; i += 256) {
        int d = i >> 3, e = i & 7;
        WgS[e][d] = Wg[i];
    }
    __syncthreads();
    int warp = tid >> 5, lane = tid & 31;
    int t = blockIdx.x * 8 + warp;
    float acc[NEXP];
#pragma unroll
    for (int e = 0; e < NEXP; e++) acc[e] = 0.f;
    const float* xr = x + (size_t)t * DIM;
    for (int j = lane; j < DIM; j += 32) {
        float xv = xr[j];
#pragma unroll
        for (int e = 0; e < NEXP; e++) acc[e] += xv * WgS[e][j];
    }
#pragma unroll
    for (int e = 0; e < NEXP; e++) {
#pragma unroll
        for (int o = 16; o > 0; o >>= 1) acc[e] += __shfl_xor_sync(0xffffffffu, acc[e], o);
    }
    if (lane == 0) {
        float best = -INFINITY, sec = -INFINITY;
        int bi = 0, si = 0;
#pragma unroll
        for (int e = 0; e < NEXP; e++) {
            float v = acc[e];
            if (v > best)     { sec = best; si = bi; best = v; bi = e; }
            else if (v > sec) { sec = v; si = e; }
        }
        float e1 = expf(sec - best);
        float s  = 1.f + e1;
        g_tok_e[2 * t] = bi;  g_tok_e[2 * t + 1] = si;
        g_tok_g[2 * t] = 1.f / s;  g_tok_g[2 * t + 1] = e1 / s;
        atomicAdd(&g_cnt[bi], 1);
        atomicAdd(&g_cnt[si], 1);
    }
}

__global__ void prefix_kernel() {
    int o = 0;
    for (int e = 0; e < NEXP; e++) { g_off[e] = o; g_cursor[e] = o; o += g_cnt[e]; }
}

__global__ void assign_kernel() {
    int t = blockIdx.x * 256 + threadIdx.x;
    int e0 = g_tok_e[2 * t], e1 = g_tok_e[2 * t + 1];
    int r0 = atomicAdd(&g_cursor[e0], 1);
    int r1 = atomicAdd(&g_cursor[e1], 1);
    g_row_tok[r0] = t; g_row_gate[r0] = g_tok_g[2 * t];
    g_row_tok[r1] = t; g_row_gate[r1] = g_tok_g[2 * t + 1];
    g_ass_row[2 * t] = r0;
    g_ass_row[2 * t + 1] = r1;
}

__device__ __forceinline__ uint32_t pack_h2(float a, float b) {
    __half2 h = __floats2half2_rn(a, b);
    return *(uint32_t*)&h;
}

// ---------------- WMMA fp16 GEMM (R9 config) + STS.128 staging ----------------
// C[m][n] = sum_k A[m][k]*B[k][n].
// G1: A[m][k] = x[g_row_tok[base+m]][k] (fp32), B = W1[e] [D][F]. H fp32 out.
// G2: A[m][k] = g_H[base+m][k] (fp32),          B = W2[e] [F][D]. O fp32 out.
// CTA tile 128x128, KC=32, double-buffered static smem; 8 warps = 4(M) x 2(N), warp tile 32x64.
// Staging: each thread owns 8-float contiguous segments -> 2 LDG.128 + 1 STS.128 per segment.
template<bool G1>
__global__ __launch_bounds__(256, 2) void moe_gemm_wmma(const float* __restrict__ x,
                                                        const float* __restrict__ W,
                                                        const float* __restrict__ bias) {
    constexpr int K    = G1 ? DIM : FDIM;
    constexpr int NOUT = G1 ? FDIM : DIM;
    constexpr int KT   = K / 32;

    __shared__ __align__(32) __half As[2][128 * 40];   // ldm 40 (80B rows, 16B-aligned)
    __shared__ __align__(32) __half Bs[2][32 * 136];   // ldm 136 (272B rows, 16B-aligned)
    __shared__ __align__(32) float  scr[8][16 * 16];

    int e   = blockIdx.z;
    int cnt = g_cnt[e];
    int m0  = blockIdx.y * 128;
    if (m0 >= cnt) return;
    int base = g_off[e];
    int n0   = blockIdx.x * 128;

    const float* Bb = W + (size_t)e * ((size_t)DIM * FDIM);

    int tid = threadIdx.x, wid = tid >> 5, lane = tid & 31;
    int wm = (wid & 3) * 32;
    int wn = (wid >> 2) * 64;

    // A segments: 128 rows x 4 segs (8 floats each) = 512 segs, 2/thread.
    int tokA[2];
#pragma unroll
    for (int q = 0; q < 2; q++) {
        int p = q * 256 + tid;
        int arow = p >> 2;
        int mr = m0 + arow; if (mr >= cnt) mr = cnt - 1;
        tokA[q] = G1 ? g_row_tok[base + mr] : (base + mr);
    }

    float4 ra[2][2], rb[2][2];
    auto gload = [&](int kt) {
#pragma unroll
        for (int q = 0; q < 2; q++) {
            int p = q * 256 + tid;
            int aseg = p & 3;
            const float* arow_p = (G1 ? (x + (size_t)tokA[q] * DIM)
                                      : (g_H + (size_t)tokA[q] * FDIM)) + kt * 32 + aseg * 8;
            ra[q][0] = *(const float4*)(arow_p);
            ra[q][1] = *(const float4*)(arow_p + 4);
            // B segments: 32 rows x 16 segs = 512 segs, 2/thread
            int brow = p >> 4, bseg = p & 15;
            const float* brow_p = Bb + (size_t)(kt * 32 + brow) * NOUT + n0 + bseg * 8;
            rb[q][0] = *(const float4*)(brow_p);
            rb[q][1] = *(const float4*)(brow_p + 4);
        }
    };
    auto sstore = [&](int s) {
#pragma unroll
        for (int q = 0; q < 2; q++) {
            int p = q * 256 + tid;
            int arow = p >> 2, aseg = p & 3;
            uint4 pa;
            pa.x = pack_h2(ra[q][0].x, ra[q][0].y);
            pa.y = pack_h2(ra[q][0].z, ra[q][0].w);
            pa.z = pack_h2(ra[q][1].x, ra[q][1].y);
            pa.w = pack_h2(ra[q][1].z, ra[q][1].w);
            *(uint4*)&As[s][arow * 40 + aseg * 8] = pa;
            int brow = p >> 4, bseg = p & 15;
            uint4 pb;
            pb.x = pack_h2(rb[q][0].x, rb[q][0].y);
            pb.y = pack_h2(rb[q][0].z, rb[q][0].w);
            pb.z = pack_h2(rb[q][1].x, rb[q][1].y);
            pb.w = pack_h2(rb[q][1].z, rb[q][1].w);
            *(uint4*)&Bs[s][brow * 136 + bseg * 8] = pb;
        }
    };

    wmma::fragment<wmma::accumulator, 16, 16, 16, float> acc[2][4];
#pragma unroll
    for (int mi = 0; mi < 2; mi++)
#pragma unroll
        for (int nj = 0; nj < 4; nj++) wmma::fill_fragment(acc[mi][nj], 0.f);

    gload(0);

#pragma unroll 1
    for (int kt = 0; kt < KT; kt++) {
        int s = kt & 1;
        __syncthreads();
        sstore(s);
        __syncthreads();
        if (kt + 1 < KT) gload(kt + 1);

#pragma unroll
        for (int kk = 0; kk < 2; kk++) {
            wmma::fragment<wmma::matrix_a, 16, 16, 16, __half, wmma::row_major> af[2];
            wmma::fragment<wmma::matrix_b, 16, 16, 16, __half, wmma::row_major> bf[4];
#pragma unroll
            for (int mi = 0; mi < 2; mi++)
                wmma::load_matrix_sync(af[mi], &As[s][(wm + mi * 16) * 40 + kk * 16], 40);
#pragma unroll
            for (int nj = 0; nj < 4; nj++)
                wmma::load_matrix_sync(bf[nj], &Bs[s][(kk * 16) * 136 + wn + nj * 16], 136);
#pragma unroll
            for (int mi = 0; mi < 2; mi++)
#pragma unroll
                for (int nj = 0; nj < 4; nj++)
                    wmma::mma_sync(acc[mi][nj], af[mi], bf[nj], acc[mi][nj]);
        }
    }

    // ---------------- vectorized epilogue via per-warp smem scratch ----------------
    __syncthreads();
    const float* be = bias + (size_t)e * NOUT + n0;
    int rr = lane >> 2;            // rows 0..7
    int cc = (lane & 3) * 4;       // float4 column chunk
#pragma unroll
    for (int mi = 0; mi < 2; mi++) {
#pragma unroll
        for (int nj = 0; nj < 4; nj++) {
            wmma::store_matrix_sync(&scr[wid][0], acc[mi][nj], 16, wmma::mem_row_major);
            __syncwarp();
            int mbase = m0 + wm + mi * 16;
#pragma unroll
            for (int h = 0; h < 2; h++) {
                int row = rr + h * 8;
                int m = mbase + row;
                if (m < cnt) {
                    int r = base + m;
                    int nc = wn + nj * 16 + cc;
                    float4 v = *(const float4*)&scr[wid][row * 16 + cc];
                    float4 bv = *(const float4*)&be[nc];
                    v.x += bv.x; v.y += bv.y; v.z += bv.z; v.w += bv.w;
                    if (G1) {
                        v.x = v.x > 0.f ? v.x : 0.f;
                        v.y = v.y > 0.f ? v.y : 0.f;
                        v.z = v.z > 0.f ? v.z : 0.f;
                        v.w = v.w > 0.f ? v.w : 0.f;
                        *(float4*)&g_H[(size_t)r * FDIM + n0 + nc] = v;
                    } else {
                        float gate = g_row_gate[r];
                        v.x = gate * __expf(v.x);
                        v.y = gate * __expf(v.y);
                        v.z = gate * __expf(v.z);
                        v.w = gate * __expf(v.w);
                        *(float4*)&g_O[(size_t)r * DIM + n0 + nc] = v;
                    }
                }
            }
            __syncwarp();
        }
    }
}

// ---------------- combine (float4-vectorized) ----------------
__global__ void combine_kernel(float* __restrict__ out) {
    int i = blockIdx.x * 256 + threadIdx.x;   // N_TOK*DIM/4 threads
    int idx = i * 4;
    int t = idx >> 9;
    int d = idx & (DIM - 1);
    int r0 = g_ass_row[2 * t];
    int r1 = g_ass_row[2 * t + 1];
    float4 a = *(const float4*)&g_O[(size_t)r0 * DIM + d];
    float4 b = *(const float4*)&g_O[(size_t)r1 * DIM + d];
    float4 v;
    float s0 = a.x + b.x, s1 = a.y + b.y, s2 = a.z + b.z, s3 = a.w + b.w;
    v.x = logf(s0 == 0.f ? EPS_F : s0);
    v.y = logf(s1 == 0.f ? EPS_F : s1);
    v.z = logf(s2 == 0.f ? EPS_F : s2);
    v.w = logf(s3 == 0.f ? EPS_F : s3);
    *(float4*)&out[idx] = v;
}

// ---------------- launch ----------------
extern "C" void kernel_launch(void* const* d_in, const int* in_sizes, int n_in,
                              void* d_out, int out_size) {
    const float* x  = (const float*)d_in[0];
    const float* Wg = (const float*)d_in[1];
    const float* W1 = (const float*)d_in[2];
    const float* b1 = (const float*)d_in[3];
    const float* W2 = (const float*)d_in[4];
    const float* b2 = (const float*)d_in[5];
    float* out = (float*)d_out;

    zero_kernel<<<1, 32>>>();
    gate_kernel<<<N_TOK / 8, 256>>>(x, Wg);
    prefix_kernel<<<1, 1>>>();
    assign_kernel<<<N_TOK / 256, 256>>>();

    moe_gemm_wmma<true ><<<dim3(FDIM / 128, 64, NEXP), 256>>>(x, W1, b1);
    moe_gemm_wmma<false><<<dim3(DIM  / 128, 64, NEXP), 256>>>(x, W2, b2);

    combine_kernel<<<(N_TOK * DIM / 4) / 256, 256>>>(out);
}

// round 12
// speedup vs baseline: 1.0460x; 1.0407x over previous
#include <cuda_runtime.h>
#include <cuda_fp16.h>
#include <mma.h>
#include <math.h>
#include <stdint.h>

using namespace nvcuda;

// Problem constants
#define N_TOK 8192
#define DIM   512
#define FDIM  2048
#define NEXP  8
#define NASS  (N_TOK * 2)
#define EPS_F 2.220446049250313e-16f

// ---------------- scratch (static device globals) ----------------
__device__ float g_H[(size_t)NASS * FDIM];   // relu(x@W1+b1), fp32
__device__ float g_O[(size_t)NASS * DIM];    // gate*exp(h@W2+b2), fp32
__device__ int   g_cnt[NEXP];                // zero-initialized; re-zeroed by combine_kernel each run
__device__ int   g_off[NEXP];
__device__ int   g_cursor[NEXP];
__device__ int   g_tok_e[N_TOK * 2];
__device__ float g_tok_g[N_TOK * 2];
__device__ int   g_row_tok[NASS];
__device__ float g_row_gate[NASS];
__device__ int   g_ass_row[N_TOK * 2];

// ---------------- gating / routing (validated; zero_kernel folded into combine) ----------------
__global__ void gate_kernel(const float* __restrict__ x, const float* __restrict__ Wg) {
    __shared__ float WgS[NEXP][DIM];
    int tid = threadIdx.x;
    for (int i = tid; i < DIM * NEXP; i += 256) {
        int d = i >> 3, e = i & 7;
        WgS[e][d] = Wg[i];
    }
    __syncthreads();
    int warp = tid >> 5, lane = tid & 31;
    int t = blockIdx.x * 8 + warp;
    float acc[NEXP];
#pragma unroll
    for (int e = 0; e < NEXP; e++) acc[e] = 0.f;
    const float* xr = x + (size_t)t * DIM;
    for (int j = lane; j < DIM; j += 32) {
        float xv = xr[j];
#pragma unroll
        for (int e = 0; e < NEXP; e++) acc[e] += xv * WgS[e][j];
    }
#pragma unroll
    for (int e = 0; e < NEXP; e++) {
#pragma unroll
        for (int o = 16; o > 0; o >>= 1) acc[e] += __shfl_xor_sync(0xffffffffu, acc[e], o);
    }
    if (lane == 0) {
        float best = -INFINITY, sec = -INFINITY;
        int bi = 0, si = 0;
#pragma unroll
        for (int e = 0; e < NEXP; e++) {
            float v = acc[e];
            if (v > best)     { sec = best; si = bi; best = v; bi = e; }
            else if (v > sec) { sec = v; si = e; }
        }
        float e1 = expf(sec - best);
        float s  = 1.f + e1;
        g_tok_e[2 * t] = bi;  g_tok_e[2 * t + 1] = si;
        g_tok_g[2 * t] = 1.f / s;  g_tok_g[2 * t + 1] = e1 / s;
        atomicAdd(&g_cnt[bi], 1);
        atomicAdd(&g_cnt[si], 1);
    }
}

__global__ void prefix_kernel() {
    int o = 0;
    for (int e = 0; e < NEXP; e++) { g_off[e] = o; g_cursor[e] = o; o += g_cnt[e]; }
}

__global__ void assign_kernel() {
    int t = blockIdx.x * 256 + threadIdx.x;
    int e0 = g_tok_e[2 * t], e1 = g_tok_e[2 * t + 1];
    int r0 = atomicAdd(&g_cursor[e0], 1);
    int r1 = atomicAdd(&g_cursor[e1], 1);
    g_row_tok[r0] = t; g_row_gate[r0] = g_tok_g[2 * t];
    g_row_tok[r1] = t; g_row_gate[r1] = g_tok_g[2 * t + 1];
    g_ass_row[2 * t] = r0;
    g_ass_row[2 * t + 1] = r1;
}

// ---------------- WMMA fp16 GEMM (exact R9 383.7us winner) ----------------
// C[m][n] = sum_k A[m][k]*B[k][n].
// G1: A[m][k] = x[g_row_tok[base+m]][k] (fp32), B = W1[e] [D][F]. H fp32 out.
// G2: A[m][k] = g_H[base+m][k] (fp32),          B = W2[e] [F][D]. O fp32 out.
// CTA tile 128x128, KC=32, double-buffered static smem; 8 warps = 4(M) x 2(N), warp tile 32x64.
template<bool G1>
__global__ __launch_bounds__(256, 2) void moe_gemm_wmma(const float* __restrict__ x,
                                                        const float* __restrict__ W,
                                                        const float* __restrict__ bias) {
    constexpr int K    = G1 ? DIM : FDIM;
    constexpr int NOUT = G1 ? FDIM : DIM;
    constexpr int KT   = K / 32;

    __shared__ __align__(32) __half As[2][128 * 40];   // ldm 40
    __shared__ __align__(32) __half Bs[2][32 * 136];   // ldm 136
    __shared__ __align__(32) float  scr[8][16 * 16];

    int e   = blockIdx.z;
    int cnt = g_cnt[e];
    int m0  = blockIdx.y * 128;
    if (m0 >= cnt) return;
    int base = g_off[e];
    int n0   = blockIdx.x * 128;

    const float* Bb = W + (size_t)e * ((size_t)DIM * FDIM);

    int tid = threadIdx.x, wid = tid >> 5, lane = tid & 31;
    int wm = (wid & 3) * 32;
    int wn = (wid >> 2) * 64;

    // A-chunk source rows (gathered once)
    int tok[4];
#pragma unroll
    for (int q = 0; q < 4; q++) {
        int ch = q * 256 + tid;
        int arow = ch >> 3;
        int mr = m0 + arow; if (mr >= cnt) mr = cnt - 1;
        tok[q] = G1 ? g_row_tok[base + mr] : (base + mr);
    }

    float4 ra[4], rb[4];
    auto gload = [&](int kt) {
#pragma unroll
        for (int q = 0; q < 4; q++) {
            int ch = q * 256 + tid;
            int ac = ch & 7;
            const float* arow_p = G1 ? (x + (size_t)tok[q] * DIM)
                                     : (g_H + (size_t)tok[q] * FDIM);
            ra[q] = *(const float4*)(arow_p + kt * 32 + ac * 4);
            int brow = ch >> 5, bc = ch & 31;
            rb[q] = *(const float4*)(Bb + (size_t)(kt * 32 + brow) * NOUT + n0 + bc * 4);
        }
    };
    auto sstore = [&](int s) {
#pragma unroll
        for (int q = 0; q < 4; q++) {
            int ch = q * 256 + tid;
            int arow = ch >> 3, ac = ch & 7;
            __half2* ap = (__half2*)&As[s][arow * 40 + ac * 4];
            ap[0] = __floats2half2_rn(ra[q].x, ra[q].y);
            ap[1] = __floats2half2_rn(ra[q].z, ra[q].w);
            int brow = ch >> 5, bc = ch & 31;
            __half2* bp = (__half2*)&Bs[s][brow * 136 + bc * 4];
            bp[0] = __floats2half2_rn(rb[q].x, rb[q].y);
            bp[1] = __floats2half2_rn(rb[q].z, rb[q].w);
        }
    };

    wmma::fragment<wmma::accumulator, 16, 16, 16, float> acc[2][4];
#pragma unroll
    for (int mi = 0; mi < 2; mi++)
#pragma unroll
        for (int nj = 0; nj < 4; nj++) wmma::fill_fragment(acc[mi][nj], 0.f);

    gload(0);

#pragma unroll 1
    for (int kt = 0; kt < KT; kt++) {
        int s = kt & 1;
        __syncthreads();
        sstore(s);
        __syncthreads();
        if (kt + 1 < KT) gload(kt + 1);

#pragma unroll
        for (int kk = 0; kk < 2; kk++) {
            wmma::fragment<wmma::matrix_a, 16, 16, 16, __half, wmma::row_major> af[2];
            wmma::fragment<wmma::matrix_b, 16, 16, 16, __half, wmma::row_major> bf[4];
#pragma unroll
            for (int mi = 0; mi < 2; mi++)
                wmma::load_matrix_sync(af[mi], &As[s][(wm + mi * 16) * 40 + kk * 16], 40);
#pragma unroll
            for (int nj = 0; nj < 4; nj++)
                wmma::load_matrix_sync(bf[nj], &Bs[s][(kk * 16) * 136 + wn + nj * 16], 136);
#pragma unroll
            for (int mi = 0; mi < 2; mi++)
#pragma unroll
                for (int nj = 0; nj < 4; nj++)
                    wmma::mma_sync(acc[mi][nj], af[mi], bf[nj], acc[mi][nj]);
        }
    }

    // ---------------- vectorized epilogue via per-warp smem scratch ----------------
    __syncthreads();
    const float* be = bias + (size_t)e * NOUT + n0;
    int rr = lane >> 2;            // rows 0..7
    int cc = (lane & 3) * 4;       // float4 column chunk
#pragma unroll
    for (int mi = 0; mi < 2; mi++) {
#pragma unroll
        for (int nj = 0; nj < 4; nj++) {
            wmma::store_matrix_sync(&scr[wid][0], acc[mi][nj], 16, wmma::mem_row_major);
            __syncwarp();
            int mbase = m0 + wm + mi * 16;
#pragma unroll
            for (int h = 0; h < 2; h++) {
                int row = rr + h * 8;
                int m = mbase + row;
                if (m < cnt) {
                    int r = base + m;
                    int nc = wn + nj * 16 + cc;
                    float4 v = *(const float4*)&scr[wid][row * 16 + cc];
                    float4 bv = *(const float4*)&be[nc];
                    v.x += bv.x; v.y += bv.y; v.z += bv.z; v.w += bv.w;
                    if (G1) {
                        v.x = v.x > 0.f ? v.x : 0.f;
                        v.y = v.y > 0.f ? v.y : 0.f;
                        v.z = v.z > 0.f ? v.z : 0.f;
                        v.w = v.w > 0.f ? v.w : 0.f;
                        *(float4*)&g_H[(size_t)r * FDIM + n0 + nc] = v;
                    } else {
                        float gate = g_row_gate[r];
                        v.x = gate * __expf(v.x);
                        v.y = gate * __expf(v.y);
                        v.z = gate * __expf(v.z);
                        v.w = gate * __expf(v.w);
                        *(float4*)&g_O[(size_t)r * DIM + n0 + nc] = v;
                    }
                }
            }
            __syncwarp();
        }
    }
}

// ---------------- combine (float4) + counter re-zero for next invocation ----------------
__global__ void combine_kernel(float* __restrict__ out) {
    int i = blockIdx.x * 256 + threadIdx.x;   // N_TOK*DIM/4 threads
    int idx = i * 4;
    int t = idx >> 9;
    int d = idx & (DIM - 1);
    int r0 = g_ass_row[2 * t];
    int r1 = g_ass_row[2 * t + 1];
    float4 a = *(const float4*)&g_O[(size_t)r0 * DIM + d];
    float4 b = *(const float4*)&g_O[(size_t)r1 * DIM + d];
    float4 v;
    float s0 = a.x + b.x, s1 = a.y + b.y, s2 = a.z + b.z, s3 = a.w + b.w;
    v.x = logf(s0 == 0.f ? EPS_F : s0);
    v.y = logf(s1 == 0.f ? EPS_F : s1);
    v.z = logf(s2 == 0.f ? EPS_F : s2);
    v.w = logf(s3 == 0.f ? EPS_F : s3);
    *(float4*)&out[idx] = v;
    // maintain invariant: g_cnt is zero at every kernel_launch entry
    if (blockIdx.x == 0 && threadIdx.x < NEXP) g_cnt[threadIdx.x] = 0;
}

// ---------------- launch ----------------
extern "C" void kernel_launch(void* const* d_in, const int* in_sizes, int n_in,
                              void* d_out, int out_size) {
    const float* x  = (const float*)d_in[0];
    const float* Wg = (const float*)d_in[1];
    const float* W1 = (const float*)d_in[2];
    const float* b1 = (const float*)d_in[3];
    const float* W2 = (const float*)d_in[4];
    const float* b2 = (const float*)d_in[5];
    float* out = (float*)d_out;

    gate_kernel<<<N_TOK / 8, 256>>>(x, Wg);       // launch 1
    prefix_kernel<<<1, 1>>>();                     // launch 2
    assign_kernel<<<N_TOK / 256, 256>>>();         // launch 3
    moe_gemm_wmma<true ><<<dim3(FDIM / 128, 64, NEXP), 256>>>(x, W1, b1);   // launch 4 -> ncu slot
    moe_gemm_wmma<false><<<dim3(DIM  / 128, 64, NEXP), 256>>>(x, W2, b2);   // launch 5
    combine_kernel<<<(N_TOK * DIM / 4) / 256, 256>>>(out);                  // launch 6
}

// round 13
// speedup vs baseline: 1.0538x; 1.0075x over previous
#include <cuda_runtime.h>
#include <cuda_fp16.h>
#include <mma.h>
#include <math.h>
#include <stdint.h>

using namespace nvcuda;

// Problem constants
#define N_TOK 8192
#define DIM   512
#define FDIM  2048
#define NEXP  8
#define NASS  (N_TOK * 2)
#define EPS_F 2.220446049250313e-16f

// ---------------- scratch (static device globals) ----------------
__device__ float g_H[(size_t)NASS * FDIM];   // relu(x@W1+b1), fp32
__device__ float g_O[(size_t)NASS * DIM];    // gate*exp(h@W2+b2), fp32
__device__ int   g_cnt[NEXP];                // zero-initialized; re-zeroed by combine_kernel each run
__device__ int   g_off[NEXP];
__device__ int   g_cursor[NEXP];
__device__ int   g_tok_e[N_TOK * 2];
__device__ float g_tok_g[N_TOK * 2];
__device__ int   g_row_tok[NASS];
__device__ float g_row_gate[NASS];
__device__ int   g_ass_row[N_TOK * 2];

// ---------------- gating / routing (validated, unchanged) ----------------
__global__ void gate_kernel(const float* __restrict__ x, const float* __restrict__ Wg) {
    __shared__ float WgS[NEXP][DIM];
    int tid = threadIdx.x;
    for (int i = tid; i < DIM * NEXP; i += 256) {
        int d = i >> 3, e = i & 7;
        WgS[e][d] = Wg[i];
    }
    __syncthreads();
    int warp = tid >> 5, lane = tid & 31;
    int t = blockIdx.x * 8 + warp;
    float acc[NEXP];
#pragma unroll
    for (int e = 0; e < NEXP; e++) acc[e] = 0.f;
    const float* xr = x + (size_t)t * DIM;
    for (int j = lane; j < DIM; j += 32) {
        float xv = xr[j];
#pragma unroll
        for (int e = 0; e < NEXP; e++) acc[e] += xv * WgS[e][j];
    }
#pragma unroll
    for (int e = 0; e < NEXP; e++) {
#pragma unroll
        for (int o = 16; o > 0; o >>= 1) acc[e] += __shfl_xor_sync(0xffffffffu, acc[e], o);
    }
    if (lane == 0) {
        float best = -INFINITY, sec = -INFINITY;
        int bi = 0, si = 0;
#pragma unroll
        for (int e = 0; e < NEXP; e++) {
            float v = acc[e];
            if (v > best)     { sec = best; si = bi; best = v; bi = e; }
            else if (v > sec) { sec = v; si = e; }
        }
        float e1 = expf(sec - best);
        float s  = 1.f + e1;
        g_tok_e[2 * t] = bi;  g_tok_e[2 * t + 1] = si;
        g_tok_g[2 * t] = 1.f / s;  g_tok_g[2 * t + 1] = e1 / s;
        atomicAdd(&g_cnt[bi], 1);
        atomicAdd(&g_cnt[si], 1);
    }
}

__global__ void prefix_kernel() {
    int o = 0;
    for (int e = 0; e < NEXP; e++) { g_off[e] = o; g_cursor[e] = o; o += g_cnt[e]; }
}

__global__ void assign_kernel() {
    int t = blockIdx.x * 256 + threadIdx.x;
    int e0 = g_tok_e[2 * t], e1 = g_tok_e[2 * t + 1];
    int r0 = atomicAdd(&g_cursor[e0], 1);
    int r1 = atomicAdd(&g_cursor[e1], 1);
    g_row_tok[r0] = t; g_row_gate[r0] = g_tok_g[2 * t];
    g_row_tok[r1] = t; g_row_gate[r1] = g_tok_g[2 * t + 1];
    g_ass_row[2 * t] = r0;
    g_ass_row[2 * t + 1] = r1;
}

// ---------------- WMMA fp16 GEMM (R12 structure) + L1-bypass staging loads ----------------
// C[m][n] = sum_k A[m][k]*B[k][n].
// G1: A[m][k] = x[g_row_tok[base+m]][k] (fp32), B = W1[e] [D][F]. H fp32 out.
// G2: A[m][k] = g_H[base+m][k] (fp32),          B = W2[e] [F][D]. O fp32 out.
// CTA tile 128x128, KC=32, double-buffered static smem; 8 warps = 4(M) x 2(N), warp tile 32x64.
// Staging global loads use __ldcg (L2-only) to keep L1tex wavefronts for LDSM/STS.
template<bool G1>
__global__ __launch_bounds__(256, 2) void moe_gemm_wmma(const float* __restrict__ x,
                                                        const float* __restrict__ W,
                                                        const float* __restrict__ bias) {
    constexpr int K    = G1 ? DIM : FDIM;
    constexpr int NOUT = G1 ? FDIM : DIM;
    constexpr int KT   = K / 32;

    __shared__ __align__(32) __half As[2][128 * 40];   // ldm 40
    __shared__ __align__(32) __half Bs[2][32 * 136];   // ldm 136
    __shared__ __align__(32) float  scr[8][16 * 16];

    int e   = blockIdx.z;
    int cnt = g_cnt[e];
    int m0  = blockIdx.y * 128;
    if (m0 >= cnt) return;
    int base = g_off[e];
    int n0   = blockIdx.x * 128;

    const float* Bb = W + (size_t)e * ((size_t)DIM * FDIM);

    int tid = threadIdx.x, wid = tid >> 5, lane = tid & 31;
    int wm = (wid & 3) * 32;
    int wn = (wid >> 2) * 64;

    // A-chunk source rows (gathered once)
    int tok[4];
#pragma unroll
    for (int q = 0; q < 4; q++) {
        int ch = q * 256 + tid;
        int arow = ch >> 3;
        int mr = m0 + arow; if (mr >= cnt) mr = cnt - 1;
        tok[q] = G1 ? g_row_tok[base + mr] : (base + mr);
    }

    float4 ra[4], rb[4];
    auto gload = [&](int kt) {
#pragma unroll
        for (int q = 0; q < 4; q++) {
            int ch = q * 256 + tid;
            int ac = ch & 7;
            const float* arow_p = G1 ? (x + (size_t)tok[q] * DIM)
                                     : (g_H + (size_t)tok[q] * FDIM);
            ra[q] = __ldcg((const float4*)(arow_p + kt * 32 + ac * 4));
            int brow = ch >> 5, bc = ch & 31;
            rb[q] = __ldcg((const float4*)(Bb + (size_t)(kt * 32 + brow) * NOUT + n0 + bc * 4));
        }
    };
    auto sstore = [&](int s) {
#pragma unroll
        for (int q = 0; q < 4; q++) {
            int ch = q * 256 + tid;
            int arow = ch >> 3, ac = ch & 7;
            __half2* ap = (__half2*)&As[s][arow * 40 + ac * 4];
            ap[0] = __floats2half2_rn(ra[q].x, ra[q].y);
            ap[1] = __floats2half2_rn(ra[q].z, ra[q].w);
            int brow = ch >> 5, bc = ch & 31;
            __half2* bp = (__half2*)&Bs[s][brow * 136 + bc * 4];
            bp[0] = __floats2half2_rn(rb[q].x, rb[q].y);
            bp[1] = __floats2half2_rn(rb[q].z, rb[q].w);
        }
    };

    wmma::fragment<wmma::accumulator, 16, 16, 16, float> acc[2][4];
#pragma unroll
    for (int mi = 0; mi < 2; mi++)
#pragma unroll
        for (int nj = 0; nj < 4; nj++) wmma::fill_fragment(acc[mi][nj], 0.f);

    gload(0);

#pragma unroll 1
    for (int kt = 0; kt < KT; kt++) {
        int s = kt & 1;
        __syncthreads();
        sstore(s);
        __syncthreads();
        if (kt + 1 < KT) gload(kt + 1);

#pragma unroll
        for (int kk = 0; kk < 2; kk++) {
            wmma::fragment<wmma::matrix_a, 16, 16, 16, __half, wmma::row_major> af[2];
            wmma::fragment<wmma::matrix_b, 16, 16, 16, __half, wmma::row_major> bf[4];
#pragma unroll
            for (int mi = 0; mi < 2; mi++)
                wmma::load_matrix_sync(af[mi], &As[s][(wm + mi * 16) * 40 + kk * 16], 40);
#pragma unroll
            for (int nj = 0; nj < 4; nj++)
                wmma::load_matrix_sync(bf[nj], &Bs[s][(kk * 16) * 136 + wn + nj * 16], 136);
#pragma unroll
            for (int mi = 0; mi < 2; mi++)
#pragma unroll
                for (int nj = 0; nj < 4; nj++)
                    wmma::mma_sync(acc[mi][nj], af[mi], bf[nj], acc[mi][nj]);
        }
    }

    // ---------------- vectorized epilogue via per-warp smem scratch ----------------
    __syncthreads();
    const float* be = bias + (size_t)e * NOUT + n0;
    int rr = lane >> 2;            // rows 0..7
    int cc = (lane & 3) * 4;       // float4 column chunk
#pragma unroll
    for (int mi = 0; mi < 2; mi++) {
#pragma unroll
        for (int nj = 0; nj < 4; nj++) {
            wmma::store_matrix_sync(&scr[wid][0], acc[mi][nj], 16, wmma::mem_row_major);
            __syncwarp();
            int mbase = m0 + wm + mi * 16;
#pragma unroll
            for (int h = 0; h < 2; h++) {
                int row = rr + h * 8;
                int m = mbase + row;
                if (m < cnt) {
                    int r = base + m;
                    int nc = wn + nj * 16 + cc;
                    float4 v = *(const float4*)&scr[wid][row * 16 + cc];
                    float4 bv = *(const float4*)&be[nc];
                    v.x += bv.x; v.y += bv.y; v.z += bv.z; v.w += bv.w;
                    if (G1) {
                        v.x = v.x > 0.f ? v.x : 0.f;
                        v.y = v.y > 0.f ? v.y : 0.f;
                        v.z = v.z > 0.f ? v.z : 0.f;
                        v.w = v.w > 0.f ? v.w : 0.f;
                        *(float4*)&g_H[(size_t)r * FDIM + n0 + nc] = v;
                    } else {
                        float gate = g_row_gate[r];
                        v.x = gate * __expf(v.x);
                        v.y = gate * __expf(v.y);
                        v.z = gate * __expf(v.z);
                        v.w = gate * __expf(v.w);
                        *(float4*)&g_O[(size_t)r * DIM + n0 + nc] = v;
                    }
                }
            }
            __syncwarp();
        }
    }
}

// ---------------- combine (float4) + counter re-zero for next invocation ----------------
__global__ void combine_kernel(float* __restrict__ out) {
    int i = blockIdx.x * 256 + threadIdx.x;   // N_TOK*DIM/4 threads
    int idx = i * 4;
    int t = idx >> 9;
    int d = idx & (DIM - 1);
    int r0 = g_ass_row[2 * t];
    int r1 = g_ass_row[2 * t + 1];
    float4 a = *(const float4*)&g_O[(size_t)r0 * DIM + d];
    float4 b = *(const float4*)&g_O[(size_t)r1 * DIM + d];
    float4 v;
    float s0 = a.x + b.x, s1 = a.y + b.y, s2 = a.z + b.z, s3 = a.w + b.w;
    v.x = logf(s0 == 0.f ? EPS_F : s0);
    v.y = logf(s1 == 0.f ? EPS_F : s1);
    v.z = logf(s2 == 0.f ? EPS_F : s2);
    v.w = logf(s3 == 0.f ? EPS_F : s3);
    *(float4*)&out[idx] = v;
    // maintain invariant: g_cnt is zero at every kernel_launch entry
    if (blockIdx.x == 0 && threadIdx.x < NEXP) g_cnt[threadIdx.x] = 0;
}

// ---------------- launch ----------------
extern "C" void kernel_launch(void* const* d_in, const int* in_sizes, int n_in,
                              void* d_out, int out_size) {
    const float* x  = (const float*)d_in[0];
    const float* Wg = (const float*)d_in[1];
    const float* W1 = (const float*)d_in[2];
    const float* b1 = (const float*)d_in[3];
    const float* W2 = (const float*)d_in[4];
    const float* b2 = (const float*)d_in[5];
    float* out = (float*)d_out;

    gate_kernel<<<N_TOK / 8, 256>>>(x, Wg);       // launch 1
    prefix_kernel<<<1, 1>>>();                     // launch 2
    assign_kernel<<<N_TOK / 256, 256>>>();         // launch 3
    moe_gemm_wmma<true ><<<dim3(FDIM / 128, 64, NEXP), 256>>>(x, W1, b1);   // launch 4 -> ncu slot
    moe_gemm_wmma<false><<<dim3(DIM  / 128, 64, NEXP), 256>>>(x, W2, b2);   // launch 5
    combine_kernel<<<(N_TOK * DIM / 4) / 256, 256>>>(out);                  // launch 6
}